// round 13
// baseline (speedup 1.0000x reference)
#include <cuda_runtime.h>
#include <cuda_bf16.h>
#include <cstdint>

// ---------------------------------------------------------------------------
// Problem constants
// ---------------------------------------------------------------------------
#define BPTS   524288
#define NLEV   16
#define TABLE  (1u << 19)
#define HDIM   256
#define INDIM  32
#define NCLS   4
#define NRES   3
#define ROWS   64           // rows per fused CTA (2 CTAs/SM co-resident)
#define HS     260          // hbuf col stride (floats)
#define WS2    264          // wbuf col stride (u32; %32==8 -> B frags conflict-free)
#define KC     32           // k-chunk per stage (16 bf16-pairs)

__constant__ float c_res[NLEV] = {16.f,20.f,25.f,32.f,40.f,50.f,64.f,80.f,
                                  101.f,128.f,161.f,203.f,256.f,322.f,406.f,512.f};
__constant__ unsigned c_prime[6] = {1u, 2654435761u, 805459861u,
                                    3674653429u, 2097192037u, 1434869437u};

// ---------------------------------------------------------------------------
// Static scratch (allocation-free rule: __device__ globals)
// ---------------------------------------------------------------------------
#define NBLK (BPTS/256)
__device__ int      g_cnt[NCLS*NBLK];
__device__ int      g_start[NCLS*NBLK];
__device__ int      g_off[NCLS+1];
__device__ int      g_idx[BPTS];
#define WPK_STRIDE ((INDIM/2)*HDIM + NRES*(HDIM/2)*HDIM)       // 102400 u32
__device__ unsigned g_wpk[NCLS*WPK_STRIDE];
__device__ unsigned g_embh[(size_t)NLEV*TABLE];                // bf16x2 tables, 32 MB

// ---------------------------------------------------------------------------
// Small helpers
// ---------------------------------------------------------------------------
__device__ __forceinline__ unsigned pkbf(float lo, float hi){
    unsigned r; asm("cvt.rn.bf16x2.f32 %0, %2, %1;" : "=r"(r) : "f"(lo), "f"(hi)); return r;
}
__device__ __forceinline__ unsigned smem_u32(const void* p){
    return (unsigned)__cvta_generic_to_shared(p);
}
__device__ __forceinline__ void cpa16(unsigned dst, const void* src, int srcsz){
    asm volatile("cp.async.ca.shared.global [%0], [%1], 16, %2;"
                 :: "r"(dst), "l"(src), "r"(srcsz));
}
__device__ __forceinline__ void cpa_commit(){ asm volatile("cp.async.commit_group;"); }
template<int N> __device__ __forceinline__ void cpa_wait(){
    asm volatile("cp.async.wait_group %0;" :: "n"(N));
}
__device__ __forceinline__ void mma16(float* d, const unsigned* a, unsigned b0, unsigned b1){
    asm volatile("mma.sync.aligned.m16n8k16.row.col.f32.bf16.bf16.f32 "
        "{%0,%1,%2,%3}, {%4,%5,%6,%7}, {%8,%9}, {%0,%1,%2,%3};"
        : "+f"(d[0]), "+f"(d[1]), "+f"(d[2]), "+f"(d[3])
        : "r"(a[0]), "r"(a[1]), "r"(a[2]), "r"(a[3]), "r"(b0), "r"(b1));
}

// ---------------------------------------------------------------------------
// K1: per-block class histogram
// ---------------------------------------------------------------------------
__global__ void k_hist(const int* __restrict__ lid, int nblk){
    __shared__ int cnt[NCLS];
    int t = threadIdx.x;
    if (t < NCLS) cnt[t] = 0;
    __syncthreads();
    int gid = blockIdx.x*256 + t;
    int c = ((unsigned)lid[gid]) & 3u;
    atomicAdd(&cnt[c], 1);
    __syncthreads();
    if (t < NCLS) g_cnt[t*nblk + blockIdx.x] = cnt[t];
}

// ---------------------------------------------------------------------------
// K2: scan -> per-block per-class start offsets + class offsets
// ---------------------------------------------------------------------------
__global__ void k_scan(int nblk, int B){
    __shared__ int s[NCLS][256];
    __shared__ int base[NCLS];
    int t = threadIdx.x;
    int per = nblk >> 8;
    int psum[NCLS];
    #pragma unroll
    for (int c = 0; c < NCLS; ++c){
        int v = 0;
        for (int j = 0; j < per; ++j) v += g_cnt[c*nblk + t*per + j];
        psum[c] = v; s[c][t] = v;
    }
    __syncthreads();
    for (int o = 1; o < 256; o <<= 1){
        int tmp[NCLS];
        #pragma unroll
        for (int c = 0; c < NCLS; ++c) tmp[c] = (t >= o) ? s[c][t-o] : 0;
        __syncthreads();
        #pragma unroll
        for (int c = 0; c < NCLS; ++c) s[c][t] += tmp[c];
        __syncthreads();
    }
    if (t == 0){
        int b = 0;
        #pragma unroll
        for (int c = 0; c < NCLS; ++c){ base[c] = b; g_off[c] = b; b += s[c][255]; }
        g_off[NCLS] = b;
    }
    __syncthreads();
    #pragma unroll
    for (int c = 0; c < NCLS; ++c){
        int run = base[c] + s[c][t] - psum[c];
        for (int j = 0; j < per; ++j){
            g_start[c*nblk + t*per + j] = run;
            run += g_cnt[c*nblk + t*per + j];
        }
    }
}

// ---------------------------------------------------------------------------
// K3: scatter -> stable class-sorted index list
// ---------------------------------------------------------------------------
__global__ void k_scatter(const int* __restrict__ lid, int nblk){
    __shared__ int wcnt[8][NCLS];
    __shared__ int wbase[8][NCLS];
    int t = threadIdx.x, lane = t & 31, w = t >> 5;
    int gid = blockIdx.x*256 + t;
    int c = ((unsigned)lid[gid]) & 3u;
    unsigned m[NCLS];
    #pragma unroll
    for (int cc = 0; cc < NCLS; ++cc) m[cc] = __ballot_sync(0xFFFFFFFFu, c == cc);
    if (lane == 0){
        #pragma unroll
        for (int cc = 0; cc < NCLS; ++cc) wcnt[w][cc] = __popc(m[cc]);
    }
    __syncthreads();
    if (t < NCLS){
        int run = 0;
        for (int ww = 0; ww < 8; ++ww){ wbase[ww][t] = run; run += wcnt[ww][t]; }
    }
    __syncthreads();
    int rank = __popc(m[c] & ((1u << lane) - 1u));
    int pos = g_start[c*nblk + blockIdx.x] + wbase[w][c] + rank;
    g_idx[pos] = gid;
}

// ---------------------------------------------------------------------------
// K4: pack weights to bf16x2 k-pairs (k even in low half)
// ---------------------------------------------------------------------------
__global__ void k_wconv(const float* __restrict__ W0, const float* __restrict__ Wres){
    int i = blockIdx.x*256 + threadIdx.x;
    if (i >= NCLS*WPK_STRIDE) return;
    int cls = i / WPK_STRIDE;
    int r   = i - cls*WPK_STRIDE;
    float a, b;
    if (r < (INDIM/2)*HDIM){
        int kp = r >> 8, n = r & 255;
        const float* base = W0 + (size_t)cls*INDIM*HDIM;
        a = base[(2*kp)*HDIM + n];
        b = base[(2*kp+1)*HDIM + n];
    } else {
        int r2 = r - (INDIM/2)*HDIM;
        int l  = r2 / ((HDIM/2)*HDIM);
        int rr = r2 - l*((HDIM/2)*HDIM);
        int kp = rr >> 8, n = rr & 255;
        const float* base = Wres + ((size_t)cls*NRES + l)*HDIM*HDIM;
        a = base[(2*kp)*HDIM + n];
        b = base[(2*kp+1)*HDIM + n];
    }
    g_wpk[i] = pkbf(a, b);
}

// ---------------------------------------------------------------------------
// K4b: convert embedding tables to bf16x2
// ---------------------------------------------------------------------------
__global__ void k_econv(const float* __restrict__ emb){
    int i = blockIdx.x*256 + threadIdx.x;
    const float2 e = __ldg((const float2*)emb + i);
    g_embh[i] = pkbf(e.x, e.y);
}

// ---------------------------------------------------------------------------
// K5: FUSED encode + per-class MLP.
// Phase 1: 256 threads hash-encode the CTA's 64 rows directly into hbuf
//          (thread t: row t&63, levels (t>>6)*4 .. +4). LSU-bound.
// Phase 2: bf16 m16n8k16 GEMM pipeline over the 4 layers. Tensor-bound.
// 2 CTAs/SM co-reside (100KB smem, <=128 regs) -> phases overlap across CTAs.
// ---------------------------------------------------------------------------
__device__ __forceinline__ void gemm64(const float* hb, int acol, const unsigned* wb,
                                       float acc[16][4], int mrow, int ncol, int lane){
    #pragma unroll
    for (int kk = 0; kk < 2; ++kk){
        int ka = acol + kk*16;
        unsigned A[4];
        {
            int r  = mrow + (lane >> 2);
            int c0 = ka + 2*(lane & 3);
            float2 p0 = *(const float2*)&hb[r*HS + c0];
            float2 p1 = *(const float2*)&hb[(r+8)*HS + c0];
            float2 p2 = *(const float2*)&hb[r*HS + c0 + 8];
            float2 p3 = *(const float2*)&hb[(r+8)*HS + c0 + 8];
            A[0] = pkbf(p0.x, p0.y);
            A[1] = pkbf(p1.x, p1.y);
            A[2] = pkbf(p2.x, p2.y);
            A[3] = pkbf(p3.x, p3.y);
        }
        const unsigned* w0 = wb + (kk*8 + (lane & 3))*WS2;
        const unsigned* w1 = w0 + 4*WS2;
        int cB = ncol + (lane >> 2);
        #pragma unroll
        for (int nf = 0; nf < 16; ++nf)
            mma16(acc[nf], A, w0[cB + nf*8], w1[cB + nf*8]);
    }
}

__global__ void __launch_bounds__(256, 2) k_fused(const float* __restrict__ x,
                                                  const float* __restrict__ b0g,
                                                  const float* __restrict__ bresg,
                                                  const float* __restrict__ scalesg,
                                                  const float* __restrict__ woutg,
                                                  const float* __restrict__ boutg,
                                                  float* __restrict__ out, int B){
    // ---- map 1D blockIdx -> (class c, block j)
    int bid = blockIdx.x;
    int c = -1, j = 0, lo0 = 0;
    {
        int acc0 = 0;
        #pragma unroll
        for (int cc = 0; cc < NCLS; ++cc){
            int lo = g_off[cc], hi = g_off[cc+1];
            int nb = (hi > lo) ? (hi - lo + ROWS - 1)/ROWS : 0;
            if (c < 0 && bid < acc0 + nb){ c = cc; j = bid - acc0; lo0 = lo; }
            acc0 += nb;
        }
    }
    if (c < 0) return;
    int r0 = lo0 + j*ROWS;
    int rend = g_off[c+1];
    int nvalid = min(ROWS, rend - r0);

    extern __shared__ float sm[];
    float*    hbuf  = sm;                              // ROWS*HS floats
    unsigned* wbuf  = (unsigned*)(hbuf + ROWS*HS);     // 2*16*WS2 u32
    float*    bias  = (float*)(wbuf + 2*(KC/2)*WS2);   // 256
    float*    wouts = bias + HDIM;                     // 256

    int tid = threadIdx.x, lane = tid & 31, w = tid >> 5;
    const unsigned* Wc = g_wpk + (size_t)c*WPK_STRIDE;

    // ---- prefetch layer-0 weights (hidden under the encode phase)
    for (int i = tid; i < (KC/2)*64; i += 256){
        int r = i >> 6, q = i & 63;
        cpa16(smem_u32(wbuf + r*WS2 + q*4), Wc + r*HDIM + q*4, 16);
    }
    cpa_commit();
    bias[tid]  = __ldg(&b0g[c*HDIM + tid]);
    wouts[tid] = __ldg(&woutg[c*HDIM + tid]);

    // ---- PHASE 1: hash-encode 64 rows into hbuf cols [0,32)
    {
        int row = tid & 63;          // 0..63
        int qtr = tid >> 6;          // 0..3 -> levels qtr*4 .. qtr*4+3
        float2* hp = (float2*)&hbuf[row*HS + qtr*8];
        if (row < nvalid){
            int orig = __ldg(&g_idx[r0 + row]);
            const float2* xp = (const float2*)(x + (size_t)orig*6);
            float2 x01 = __ldg(xp), x23 = __ldg(xp+1), x45 = __ldg(xp+2);
            float xc[6] = {x01.x, x01.y, x23.x, x23.y, x45.x, x45.y};
            #pragma unroll
            for (int d = 0; d < 6; ++d) xc[d] = fminf(fmaxf(xc[d], 0.f), 1.f);

            for (int lq = 0; lq < 4; ++lq){
                int lvl = qtr*4 + lq;
                float resf = c_res[lvl];
                float grid = 1.0f / resf;
                float g1 = grid + 1e-6f;
                unsigned u[6], ex[6];
                float wv[6];
                #pragma unroll
                for (int d = 0; d < 6; ++d){
                    float t  = xc[d]*resf;
                    float bf = floorf(t);
                    float vmin = bf*grid;
                    float wd = (xc[d] - vmin) / g1;
                    wv[d] = fminf(fmaxf(wd, 0.f), 1.f);
                    unsigned uu = (unsigned)(int)bf * c_prime[d];
                    u[d] = uu;
                    ex[d] = uu ^ (uu + c_prime[d]);
                }
                unsigned h0 = u[0]^u[1]^u[2]^u[3]^u[4]^u[5];
                float wlo[8], whi[8];
                #pragma unroll
                for (int k = 0; k < 8; ++k){
                    wlo[k] = ((k&1)?wv[0]:1.f-wv[0]) * ((k&2)?wv[1]:1.f-wv[1]) * ((k&4)?wv[2]:1.f-wv[2]);
                    whi[k] = ((k&1)?wv[3]:1.f-wv[3]) * ((k&2)?wv[4]:1.f-wv[4]) * ((k&4)?wv[5]:1.f-wv[5]);
                }
                const unsigned* eb = g_embh + (size_t)lvl*TABLE;
                float a0 = 0.f, a1 = 0.f;
                // corner bit b -> weight dim b (LSB conv), hash dim 5-b (MSB conv)
                #pragma unroll
                for (int jj = 0; jj < 8; ++jj){        // corner bits 3..5
                    unsigned hj = h0 ^ ((jj&1)?ex[2]:0u) ^ ((jj&2)?ex[1]:0u) ^ ((jj&4)?ex[0]:0u);
                    float wj = whi[jj];
                    #pragma unroll
                    for (int k = 0; k < 8; ++k){       // corner bits 0..2
                        unsigned hv = hj ^ ((k&1)?ex[5]:0u) ^ ((k&2)?ex[4]:0u) ^ ((k&4)?ex[3]:0u);
                        unsigned pv = __ldg(eb + (hv & (TABLE-1u)));
                        float f0 = __uint_as_float(pv << 16);
                        float f1 = __uint_as_float(pv & 0xFFFF0000u);
                        float wk = wlo[k]*wj;
                        a0 = fmaf(wk, f0, a0);
                        a1 = fmaf(wk, f1, a1);
                    }
                }
                hp[lq] = make_float2(a0, a1);
            }
        } else {
            #pragma unroll
            for (int lq = 0; lq < 4; ++lq) hp[lq] = make_float2(0.f, 0.f);
        }
    }
    cpa_wait<0>();
    __syncthreads();

    // ---- PHASE 2: GEMM pipeline
    int mrow = (w >> 1)*16;      // 4 row-groups of 16
    int ncol = (w & 1)*128;      // 2 col-groups of 128
    float acc[16][4];

    // layer 0: h = relu(enc @ W0 + b0)
    #pragma unroll
    for (int nf = 0; nf < 16; ++nf)
        #pragma unroll
        for (int q = 0; q < 4; ++q) acc[nf][q] = 0.f;
    gemm64(hbuf, 0, wbuf, acc, mrow, ncol, lane);
    __syncthreads();
    #pragma unroll
    for (int nf = 0; nf < 16; ++nf){
        int r  = mrow + (lane >> 2);
        int cb = ncol + nf*8 + 2*(lane & 3);
        hbuf[r*HS + cb]       = fmaxf(acc[nf][0] + bias[cb],     0.f);
        hbuf[r*HS + cb + 1]   = fmaxf(acc[nf][1] + bias[cb+1],   0.f);
        hbuf[(r+8)*HS + cb]   = fmaxf(acc[nf][2] + bias[cb],     0.f);
        hbuf[(r+8)*HS + cb+1] = fmaxf(acc[nf][3] + bias[cb+1],   0.f);
    }
    __syncthreads();

    // residual layers: h = scale*relu(h @ W + b) + h
    for (int l = 0; l < NRES; ++l){
        const unsigned* Wl = Wc + (INDIM/2)*HDIM + l*(HDIM/2)*HDIM;
        float sc = __ldg(&scalesg[c*NRES + l]);
        bias[tid] = __ldg(&bresg[(c*NRES + l)*HDIM + tid]);
        #pragma unroll
        for (int nf = 0; nf < 16; ++nf)
            #pragma unroll
            for (int q = 0; q < 4; ++q) acc[nf][q] = 0.f;

        for (int i = tid; i < (KC/2)*64; i += 256){
            int r = i >> 6, q = i & 63;
            cpa16(smem_u32(wbuf + r*WS2 + q*4), Wl + r*HDIM + q*4, 16);
        }
        cpa_commit();
        for (int s = 0; s < 8; ++s){
            if (s < 7){
                const unsigned* src = Wl + (s+1)*(KC/2)*HDIM;
                unsigned* dst = wbuf + ((s+1) & 1)*(KC/2)*WS2;
                for (int i = tid; i < (KC/2)*64; i += 256){
                    int r = i >> 6, q = i & 63;
                    cpa16(smem_u32(dst + r*WS2 + q*4), src + r*HDIM + q*4, 16);
                }
                cpa_commit();
                cpa_wait<1>();
            } else {
                cpa_wait<0>();
            }
            __syncthreads();
            gemm64(hbuf, s*KC, wbuf + (s & 1)*(KC/2)*WS2, acc, mrow, ncol, lane);
            __syncthreads();
        }
        #pragma unroll
        for (int nf = 0; nf < 16; ++nf){
            int r  = mrow + (lane >> 2);
            int cb = ncol + nf*8 + 2*(lane & 3);
            hbuf[r*HS + cb]       = fmaf(sc, fmaxf(acc[nf][0] + bias[cb],   0.f), hbuf[r*HS + cb]);
            hbuf[r*HS + cb+1]     = fmaf(sc, fmaxf(acc[nf][1] + bias[cb+1], 0.f), hbuf[r*HS + cb+1]);
            hbuf[(r+8)*HS + cb]   = fmaf(sc, fmaxf(acc[nf][2] + bias[cb],   0.f), hbuf[(r+8)*HS + cb]);
            hbuf[(r+8)*HS + cb+1] = fmaf(sc, fmaxf(acc[nf][3] + bias[cb+1], 0.f), hbuf[(r+8)*HS + cb+1]);
        }
        __syncthreads();
    }

    // output layer: out = h @ Wout + bout (8 rows per warp, shfl reduce)
    float bo = __ldg(&boutg[c]);
    #pragma unroll
    for (int rr = 0; rr < 8; ++rr){
        int r = w*8 + rr;
        float v = 0.f;
        #pragma unroll
        for (int q = 0; q < 8; ++q)
            v = fmaf(hbuf[r*HS + q*32 + lane], wouts[q*32 + lane], v);
        #pragma unroll
        for (int o = 16; o > 0; o >>= 1) v += __shfl_xor_sync(0xFFFFFFFFu, v, o);
        if (lane == 0 && r < nvalid)
            out[g_idx[r0 + r]] = v + bo;
    }
}

// ---------------------------------------------------------------------------
// launch: single stream, 6 kernels (no streams/events — overlap is intra-SM)
// ---------------------------------------------------------------------------
extern "C" void kernel_launch(void* const* d_in, const int* in_sizes, int n_in,
                              void* d_out, int out_size){
    const float* x      = (const float*)d_in[0];
    const int*   lid    = (const int*)  d_in[1];
    const float* emb    = (const float*)d_in[2];
    const float* W0     = (const float*)d_in[3];
    const float* b0     = (const float*)d_in[4];
    const float* Wres   = (const float*)d_in[5];
    const float* bres   = (const float*)d_in[6];
    const float* scales = (const float*)d_in[7];
    const float* Wout   = (const float*)d_in[8];
    const float* bout   = (const float*)d_in[9];
    float* out = (float*)d_out;

    int B = in_sizes[1];
    int nblk = B / 256;

    int smem_bytes = (ROWS*HS + 2*HDIM) * (int)sizeof(float)
                   + 2*(KC/2)*WS2 * (int)sizeof(unsigned);
    cudaFuncSetAttribute(k_fused, cudaFuncAttributeMaxDynamicSharedMemorySize, smem_bytes);

    k_hist   <<<nblk, 256>>>(lid, nblk);
    k_scan   <<<1,    256>>>(nblk, B);
    k_scatter<<<nblk, 256>>>(lid, nblk);
    k_wconv  <<<(NCLS*WPK_STRIDE + 255)/256, 256>>>(W0, Wres);
    k_econv  <<<(NLEV*TABLE)/256, 256>>>(emb);
    int grid = B/ROWS + NCLS;
    k_fused  <<<grid, 256, smem_bytes>>>(x, b0, bres, scales, Wout, bout, out, B);
}

// round 17
// speedup vs baseline: 1.5342x; 1.5342x over previous
#include <cuda_runtime.h>
#include <cuda_bf16.h>
#include <cstdint>

// ---------------------------------------------------------------------------
// Problem constants
// ---------------------------------------------------------------------------
#define BPTS   524288
#define NLEV   16
#define TABLE  (1u << 19)
#define HDIM   256
#define INDIM  32
#define NCLS   4
#define NRES   3
#define ROWS   128          // rows per MLP CTA
#define HSB    264          // h row stride in bf16 (132 words; 132%32==4 -> LDSM conflict-free)
#define HW     132          // h row stride in u32 words
#define WS2    264          // wbuf col stride (u32; %32==8 -> B frags conflict-free)
#define KC     32           // k-chunk per stage (16 bf16-pairs)

__constant__ float c_res[NLEV] = {16.f,20.f,25.f,32.f,40.f,50.f,64.f,80.f,
                                  101.f,128.f,161.f,203.f,256.f,322.f,406.f,512.f};
__constant__ unsigned c_prime[6] = {1u, 2654435761u, 805459861u,
                                    3674653429u, 2097192037u, 1434869437u};

// ---------------------------------------------------------------------------
// Static scratch (allocation-free rule: __device__ globals)
// ---------------------------------------------------------------------------
#define NBLK (BPTS/256)
__device__ int      g_cnt[NCLS*NBLK];
__device__ int      g_start[NCLS*NBLK];
__device__ int      g_off[NCLS+1];
__device__ int      g_idx[BPTS];
__device__ unsigned g_encH[(size_t)BPTS*NLEV];                 // bf16x2 enc, 32 MB
#define WPK_STRIDE ((INDIM/2)*HDIM + NRES*(HDIM/2)*HDIM)       // 102400 u32
__device__ unsigned g_wpk[NCLS*WPK_STRIDE];
__device__ unsigned g_embh[(size_t)NLEV*TABLE];                // bf16x2 tables, 32 MB

// ---------------------------------------------------------------------------
// Small helpers
// ---------------------------------------------------------------------------
__device__ __forceinline__ unsigned pkbf(float lo, float hi){
    unsigned r; asm("cvt.rn.bf16x2.f32 %0, %2, %1;" : "=r"(r) : "f"(lo), "f"(hi)); return r;
}
__device__ __forceinline__ float bfl(unsigned u){ return __uint_as_float(u << 16); }
__device__ __forceinline__ float bfh(unsigned u){ return __uint_as_float(u & 0xFFFF0000u); }
// split (a,b) into hi word + lo (residual) word
__device__ __forceinline__ unsigned pksplit(float a, float b, unsigned& lo){
    unsigned hi = pkbf(a, b);
    lo = pkbf(a - bfl(hi), b - bfh(hi));
    return hi;
}
__device__ __forceinline__ unsigned smem_u32(const void* p){
    return (unsigned)__cvta_generic_to_shared(p);
}
__device__ __forceinline__ void cpa16(unsigned dst, const void* src, int srcsz){
    asm volatile("cp.async.ca.shared.global [%0], [%1], 16, %2;"
                 :: "r"(dst), "l"(src), "r"(srcsz));
}
__device__ __forceinline__ void cpa_commit(){ asm volatile("cp.async.commit_group;"); }
template<int N> __device__ __forceinline__ void cpa_wait(){
    asm volatile("cp.async.wait_group %0;" :: "n"(N));
}
__device__ __forceinline__ void mma16(float* d, const unsigned* a, unsigned b0, unsigned b1){
    asm volatile("mma.sync.aligned.m16n8k16.row.col.f32.bf16.bf16.f32 "
        "{%0,%1,%2,%3}, {%4,%5,%6,%7}, {%8,%9}, {%0,%1,%2,%3};"
        : "+f"(d[0]), "+f"(d[1]), "+f"(d[2]), "+f"(d[3])
        : "r"(a[0]), "r"(a[1]), "r"(a[2]), "r"(a[3]), "r"(b0), "r"(b1));
}
__device__ __forceinline__ void ldsm4(unsigned* A, unsigned addr){
    asm volatile("ldmatrix.sync.aligned.m8n8.x4.shared.b16 {%0,%1,%2,%3}, [%4];"
        : "=r"(A[0]), "=r"(A[1]), "=r"(A[2]), "=r"(A[3]) : "r"(addr));
}

// ---------------------------------------------------------------------------
// K1: per-block class histogram
// ---------------------------------------------------------------------------
__global__ void k_hist(const int* __restrict__ lid, int nblk){
    __shared__ int cnt[NCLS];
    int t = threadIdx.x;
    if (t < NCLS) cnt[t] = 0;
    __syncthreads();
    int gid = blockIdx.x*256 + t;
    int c = ((unsigned)lid[gid]) & 3u;
    atomicAdd(&cnt[c], 1);
    __syncthreads();
    if (t < NCLS) g_cnt[t*nblk + blockIdx.x] = cnt[t];
}

// ---------------------------------------------------------------------------
// K2: scan -> per-block per-class start offsets + class offsets
// ---------------------------------------------------------------------------
__global__ void k_scan(int nblk, int B){
    __shared__ int s[NCLS][256];
    __shared__ int base[NCLS];
    int t = threadIdx.x;
    int per = nblk >> 8;
    int psum[NCLS];
    #pragma unroll
    for (int c = 0; c < NCLS; ++c){
        int v = 0;
        for (int j = 0; j < per; ++j) v += g_cnt[c*nblk + t*per + j];
        psum[c] = v; s[c][t] = v;
    }
    __syncthreads();
    for (int o = 1; o < 256; o <<= 1){
        int tmp[NCLS];
        #pragma unroll
        for (int c = 0; c < NCLS; ++c) tmp[c] = (t >= o) ? s[c][t-o] : 0;
        __syncthreads();
        #pragma unroll
        for (int c = 0; c < NCLS; ++c) s[c][t] += tmp[c];
        __syncthreads();
    }
    if (t == 0){
        int b = 0;
        #pragma unroll
        for (int c = 0; c < NCLS; ++c){ base[c] = b; g_off[c] = b; b += s[c][255]; }
        g_off[NCLS] = b;
    }
    __syncthreads();
    #pragma unroll
    for (int c = 0; c < NCLS; ++c){
        int run = base[c] + s[c][t] - psum[c];
        for (int j = 0; j < per; ++j){
            g_start[c*nblk + t*per + j] = run;
            run += g_cnt[c*nblk + t*per + j];
        }
    }
}

// ---------------------------------------------------------------------------
// K3: scatter -> stable class-sorted index list
// ---------------------------------------------------------------------------
__global__ void k_scatter(const int* __restrict__ lid, int nblk){
    __shared__ int wcnt[8][NCLS];
    __shared__ int wbase[8][NCLS];
    int t = threadIdx.x, lane = t & 31, w = t >> 5;
    int gid = blockIdx.x*256 + t;
    int c = ((unsigned)lid[gid]) & 3u;
    unsigned m[NCLS];
    #pragma unroll
    for (int cc = 0; cc < NCLS; ++cc) m[cc] = __ballot_sync(0xFFFFFFFFu, c == cc);
    if (lane == 0){
        #pragma unroll
        for (int cc = 0; cc < NCLS; ++cc) wcnt[w][cc] = __popc(m[cc]);
    }
    __syncthreads();
    if (t < NCLS){
        int run = 0;
        for (int ww = 0; ww < 8; ++ww){ wbase[ww][t] = run; run += wcnt[ww][t]; }
    }
    __syncthreads();
    int rank = __popc(m[c] & ((1u << lane) - 1u));
    int pos = g_start[c*nblk + blockIdx.x] + wbase[w][c] + rank;
    g_idx[pos] = gid;
}

// ---------------------------------------------------------------------------
// K4: pack weights to bf16x2 k-pairs (k even in low half)
// ---------------------------------------------------------------------------
__global__ void k_wconv(const float* __restrict__ W0, const float* __restrict__ Wres){
    int i = blockIdx.x*256 + threadIdx.x;
    if (i >= NCLS*WPK_STRIDE) return;
    int cls = i / WPK_STRIDE;
    int r   = i - cls*WPK_STRIDE;
    float a, b;
    if (r < (INDIM/2)*HDIM){
        int kp = r >> 8, n = r & 255;
        const float* base = W0 + (size_t)cls*INDIM*HDIM;
        a = base[(2*kp)*HDIM + n];
        b = base[(2*kp+1)*HDIM + n];
    } else {
        int r2 = r - (INDIM/2)*HDIM;
        int l  = r2 / ((HDIM/2)*HDIM);
        int rr = r2 - l*((HDIM/2)*HDIM);
        int kp = rr >> 8, n = rr & 255;
        const float* base = Wres + ((size_t)cls*NRES + l)*HDIM*HDIM;
        a = base[(2*kp)*HDIM + n];
        b = base[(2*kp+1)*HDIM + n];
    }
    g_wpk[i] = pkbf(a, b);
}

// ---------------------------------------------------------------------------
// K4b: convert embedding tables to bf16x2
// ---------------------------------------------------------------------------
__global__ void k_econv(const float* __restrict__ emb){
    int i = blockIdx.x*256 + threadIdx.x;
    const float2 e = __ldg((const float2*)emb + i);
    g_embh[i] = pkbf(e.x, e.y);
}

// ---------------------------------------------------------------------------
// K5: multi-res hash encoding (bf16x2 tables), bf16x2 output, sorted order
// ---------------------------------------------------------------------------
__global__ void __launch_bounds__(256) k_encode(const float* __restrict__ x){
    int p = blockIdx.x*256 + threadIdx.x;
    int orig = __ldg(&g_idx[p]);
    const float2* xp = (const float2*)(x + (size_t)orig*6);
    float2 x01 = __ldg(xp), x23 = __ldg(xp+1), x45 = __ldg(xp+2);
    float xc[6] = {x01.x, x01.y, x23.x, x23.y, x45.x, x45.y};
    #pragma unroll
    for (int d = 0; d < 6; ++d) xc[d] = fminf(fmaxf(xc[d], 0.f), 1.f);

    unsigned* op = g_encH + (size_t)p*NLEV;

    for (int lvl = 0; lvl < NLEV; ++lvl){
        float resf = c_res[lvl];
        float grid = 1.0f / resf;
        float g1 = grid + 1e-6f;
        unsigned u[6], ex[6];
        float wv[6];
        #pragma unroll
        for (int d = 0; d < 6; ++d){
            float t  = xc[d]*resf;
            float bf = floorf(t);
            float vmin = bf*grid;
            float wd = (xc[d] - vmin) / g1;
            wv[d] = fminf(fmaxf(wd, 0.f), 1.f);
            unsigned uu = (unsigned)(int)bf * c_prime[d];
            u[d] = uu;
            ex[d] = uu ^ (uu + c_prime[d]);
        }
        unsigned h0 = u[0]^u[1]^u[2]^u[3]^u[4]^u[5];
        float wlo[8], whi[8];
        #pragma unroll
        for (int k = 0; k < 8; ++k){
            wlo[k] = ((k&1)?wv[0]:1.f-wv[0]) * ((k&2)?wv[1]:1.f-wv[1]) * ((k&4)?wv[2]:1.f-wv[2]);
            whi[k] = ((k&1)?wv[3]:1.f-wv[3]) * ((k&2)?wv[4]:1.f-wv[4]) * ((k&4)?wv[5]:1.f-wv[5]);
        }
        const unsigned* eb = g_embh + (size_t)lvl*TABLE;
        float a0 = 0.f, a1 = 0.f;
        // corner bit b -> weight dim b (LSB conv), hash dim 5-b (MSB conv)
        #pragma unroll
        for (int j = 0; j < 8; ++j){           // corner bits 3..5
            unsigned hj = h0 ^ ((j&1)?ex[2]:0u) ^ ((j&2)?ex[1]:0u) ^ ((j&4)?ex[0]:0u);
            float wj = whi[j];
            #pragma unroll
            for (int k = 0; k < 8; ++k){       // corner bits 0..2
                unsigned hv = hj ^ ((k&1)?ex[5]:0u) ^ ((k&2)?ex[4]:0u) ^ ((k&4)?ex[3]:0u);
                unsigned pv = __ldg(eb + (hv & (TABLE-1u)));
                float wk = wlo[k]*wj;
                a0 = fmaf(wk, bfl(pv), a0);
                a1 = fmaf(wk, bfh(pv), a1);
            }
        }
        __stcs(op + lvl, pkbf(a0, a1));        // streaming bf16x2 store
    }
}

// ---------------------------------------------------------------------------
// K6: per-class MLP. h stored as hi+lo bf16x2 planes:
//   hi = bf16(h)        -> ldmatrix.x4 A-operand (same numerics as R6 pkbf)
//   lo = bf16(h - hi)   -> carry compensation: hi+lo ~ fp32 h
// ---------------------------------------------------------------------------
__device__ __forceinline__ void gemm_stage16(unsigned hb, int acol, const unsigned* wb,
                                             float acc[2][16][4], int mrow, int ncol, int lane){
    int lrow = lane & 7, lsel = lane >> 3;
    int rofs = (lsel & 1) ? 8 : 0;
    int cofs = (lsel & 2) ? 8 : 0;
    #pragma unroll
    for (int kk = 0; kk < 2; ++kk){
        int ka = acol + kk*16;
        unsigned A[2][4];
        #pragma unroll
        for (int m = 0; m < 2; ++m){
            int r = mrow + m*16 + rofs + lrow;
            ldsm4(A[m], hb + (unsigned)((r*HSB + ka + cofs)*2));
        }
        const unsigned* w0 = wb + (kk*8 + (lane & 3))*WS2;
        const unsigned* w1 = w0 + 4*WS2;
        int cB = ncol + (lane >> 2);
        #pragma unroll
        for (int nf = 0; nf < 16; ++nf){
            unsigned b0 = w0[cB + nf*8];
            unsigned b1 = w1[cB + nf*8];
            mma16(acc[0][nf], A[0], b0, b1);
            mma16(acc[1][nf], A[1], b0, b1);
        }
    }
}

__global__ void __launch_bounds__(256, 1) k_mlp(const float* __restrict__ b0g,
                                                const float* __restrict__ bresg,
                                                const float* __restrict__ scalesg,
                                                const float* __restrict__ woutg,
                                                const float* __restrict__ boutg,
                                                float* __restrict__ out, int B){
    // ---- map 1D blockIdx -> (class c, block j): exact grid, no phantoms
    int bid = blockIdx.x;
    int c = -1, j = 0, lo0 = 0;
    {
        int acc0 = 0;
        #pragma unroll
        for (int cc = 0; cc < NCLS; ++cc){
            int lo = g_off[cc], hi = g_off[cc+1];
            int nb = (hi > lo) ? (hi - lo + ROWS - 1)/ROWS : 0;
            if (c < 0 && bid < acc0 + nb){ c = cc; j = bid - acc0; lo0 = lo; }
            acc0 += nb;
        }
    }
    if (c < 0) return;
    int r0 = lo0 + j*ROWS;
    int rend = g_off[c+1];
    int nvalid = min(ROWS, rend - r0);

    extern __shared__ float sm[];
    unsigned* hbw   = (unsigned*)sm;                   // ROWS*HW u32 (hi plane)
    unsigned* hlo   = hbw + ROWS*HW;                   // ROWS*HW u32 (lo plane)
    unsigned* wbuf  = hlo + ROWS*HW;                   // 2*16*WS2 u32
    float*    bias  = (float*)(wbuf + 2*(KC/2)*WS2);   // 256
    float*    wouts = bias + HDIM;                     // 256
    unsigned  hb    = smem_u32(hbw);

    int tid = threadIdx.x, lane = tid & 31, w = tid >> 5;
    const unsigned* Wc = g_wpk + (size_t)c*WPK_STRIDE;

    // ---- stage enc (bf16) -> hi plane cols [0,32), layer0 weights -> wbuf[0]
    for (int i = tid; i < ROWS*4; i += 256){           // 4x16B per row
        int r = i >> 2, q = i & 3;
        int src_row = min(r0 + r, B - 1);
        const unsigned* g = g_encH + (size_t)src_row*NLEV + q*4;
        cpa16(hb + (unsigned)(r*HSB*2 + q*16), g, (r < nvalid) ? 16 : 0);
    }
    for (int i = tid; i < (KC/2)*64; i += 256){        // 16 pair-rows x 64 16B-chunks
        int r = i >> 6, q = i & 63;
        cpa16(smem_u32(wbuf + r*WS2 + q*4), Wc + r*HDIM + q*4, 16);
    }
    bias[tid]  = __ldg(&b0g[c*HDIM + tid]);
    wouts[tid] = __ldg(&woutg[c*HDIM + tid]);
    cpa_commit();
    cpa_wait<0>();
    __syncthreads();

    int mrow = (w >> 1)*32;      // 4 row-groups of 32
    int ncol = (w & 1)*128;      // 2 col-groups of 128
    float acc[2][16][4];

    // ---- layer 0: h = relu(enc @ W0 + b0); write hi+lo
    #pragma unroll
    for (int m = 0; m < 2; ++m)
        #pragma unroll
        for (int nf = 0; nf < 16; ++nf)
            #pragma unroll
            for (int q = 0; q < 4; ++q) acc[m][nf][q] = 0.f;
    gemm_stage16(hb, 0, wbuf, acc, mrow, ncol, lane);
    __syncthreads();   // all A reads of enc complete before overwriting h planes
    #pragma unroll
    for (int m = 0; m < 2; ++m)
        #pragma unroll
        for (int nf = 0; nf < 16; ++nf){
            int r  = mrow + m*16 + (lane >> 2);
            int cb = ncol + nf*8 + 2*(lane & 3);
            int wi = cb >> 1;
            float b0v = bias[cb], b1v = bias[cb+1];
            unsigned l0, l1;
            unsigned h0 = pksplit(fmaxf(acc[m][nf][0] + b0v, 0.f),
                                  fmaxf(acc[m][nf][1] + b1v, 0.f), l0);
            unsigned h1 = pksplit(fmaxf(acc[m][nf][2] + b0v, 0.f),
                                  fmaxf(acc[m][nf][3] + b1v, 0.f), l1);
            hbw[r*HW + wi]     = h0;  hlo[r*HW + wi]     = l0;
            hbw[(r+8)*HW + wi] = h1;  hlo[(r+8)*HW + wi] = l1;
        }
    __syncthreads();

    // ---- residual layers: h = scale*relu(h @ W + b) + h  (carry = hi+lo)
    for (int l = 0; l < NRES; ++l){
        const unsigned* Wl = Wc + (INDIM/2)*HDIM + l*(HDIM/2)*HDIM;
        float sc = __ldg(&scalesg[c*NRES + l]);
        bias[tid] = __ldg(&bresg[(c*NRES + l)*HDIM + tid]);
        #pragma unroll
        for (int m = 0; m < 2; ++m)
            #pragma unroll
            for (int nf = 0; nf < 16; ++nf)
                #pragma unroll
                for (int q = 0; q < 4; ++q) acc[m][nf][q] = 0.f;

        for (int i = tid; i < (KC/2)*64; i += 256){
            int r = i >> 6, q = i & 63;
            cpa16(smem_u32(wbuf + r*WS2 + q*4), Wl + r*HDIM + q*4, 16);
        }
        cpa_commit();
        for (int s = 0; s < 8; ++s){
            if (s < 7){
                const unsigned* src = Wl + (s+1)*(KC/2)*HDIM;
                unsigned* dst = wbuf + ((s+1) & 1)*(KC/2)*WS2;
                for (int i = tid; i < (KC/2)*64; i += 256){
                    int r = i >> 6, q = i & 63;
                    cpa16(smem_u32(dst + r*WS2 + q*4), src + r*HDIM + q*4, 16);
                }
                cpa_commit();
                cpa_wait<1>();
            } else {
                cpa_wait<0>();
            }
            __syncthreads();
            gemm_stage16(hb, s*KC, wbuf + (s & 1)*(KC/2)*WS2, acc, mrow, ncol, lane);
            __syncthreads();
        }
        // epilogue: carry = hi+lo (fp32-quality), update, re-split
        #pragma unroll
        for (int m = 0; m < 2; ++m)
            #pragma unroll
            for (int nf = 0; nf < 16; ++nf){
                int r  = mrow + m*16 + (lane >> 2);
                int cb = ncol + nf*8 + 2*(lane & 3);
                int wi = cb >> 1;
                float b0v = bias[cb], b1v = bias[cb+1];
                unsigned o0 = hbw[r*HW + wi],     e0 = hlo[r*HW + wi];
                unsigned o1 = hbw[(r+8)*HW + wi], e1 = hlo[(r+8)*HW + wi];
                float h00 = fmaf(sc, fmaxf(acc[m][nf][0] + b0v, 0.f), bfl(o0) + bfl(e0));
                float h01 = fmaf(sc, fmaxf(acc[m][nf][1] + b1v, 0.f), bfh(o0) + bfh(e0));
                float h10 = fmaf(sc, fmaxf(acc[m][nf][2] + b0v, 0.f), bfl(o1) + bfl(e1));
                float h11 = fmaf(sc, fmaxf(acc[m][nf][3] + b1v, 0.f), bfh(o1) + bfh(e1));
                unsigned l0n, l1n;
                unsigned h0n = pksplit(h00, h01, l0n);
                unsigned h1n = pksplit(h10, h11, l1n);
                hbw[r*HW + wi]     = h0n;  hlo[r*HW + wi]     = l0n;
                hbw[(r+8)*HW + wi] = h1n;  hlo[(r+8)*HW + wi] = l1n;
            }
        __syncthreads();
    }

    // ---- output layer: out = (hi+lo) @ Wout + bout (16 rows/warp, shfl reduce)
    float bo = __ldg(&boutg[c]);
    #pragma unroll
    for (int rr = 0; rr < 16; ++rr){
        int r = w*16 + rr;
        float v = 0.f;
        #pragma unroll
        for (int q = 0; q < 4; ++q){
            int wi = q*32 + lane;
            unsigned hw = hbw[r*HW + wi];
            unsigned le = hlo[r*HW + wi];
            v = fmaf(bfl(hw) + bfl(le), wouts[2*wi],     v);
            v = fmaf(bfh(hw) + bfh(le), wouts[2*wi + 1], v);
        }
        #pragma unroll
        for (int o = 16; o > 0; o >>= 1) v += __shfl_xor_sync(0xFFFFFFFFu, v, o);
        if (lane == 0 && r < nvalid)
            out[g_idx[r0 + r]] = v + bo;
    }
}

// ---------------------------------------------------------------------------
// launch: single stream, 7 kernels (serial)
// ---------------------------------------------------------------------------
extern "C" void kernel_launch(void* const* d_in, const int* in_sizes, int n_in,
                              void* d_out, int out_size){
    const float* x      = (const float*)d_in[0];
    const int*   lid    = (const int*)  d_in[1];
    const float* emb    = (const float*)d_in[2];
    const float* W0     = (const float*)d_in[3];
    const float* b0     = (const float*)d_in[4];
    const float* Wres   = (const float*)d_in[5];
    const float* bres   = (const float*)d_in[6];
    const float* scales = (const float*)d_in[7];
    const float* Wout   = (const float*)d_in[8];
    const float* bout   = (const float*)d_in[9];
    float* out = (float*)d_out;

    int B = in_sizes[1];
    int nblk = B / 256;

    int smem_bytes = (2*ROWS*HW + 2*(KC/2)*WS2) * (int)sizeof(unsigned)
                   + 2*HDIM * (int)sizeof(float);
    cudaFuncSetAttribute(k_mlp, cudaFuncAttributeMaxDynamicSharedMemorySize, smem_bytes);

    k_hist   <<<nblk, 256>>>(lid, nblk);
    k_scan   <<<1,    256>>>(nblk, B);
    k_scatter<<<nblk, 256>>>(lid, nblk);
    k_wconv  <<<(NCLS*WPK_STRIDE + 255)/256, 256>>>(W0, Wres);
    k_econv  <<<(NLEV*TABLE)/256, 256>>>(emb);
    k_encode <<<nblk, 256>>>(x);
    int grid = B/ROWS + NCLS;
    k_mlp    <<<grid, 256, smem_bytes>>>(b0, bres, scales, Wout, bout, out, B);
}